// round 1
// baseline (speedup 1.0000x reference)
#include <cuda_runtime.h>
#include <cuda_fp16.h>
#include <cstdint>

#define B_SZ   64
#define IN_F   8192
#define OUT_F  8192
#define NNZ    262144
#define K8     8

// ---------------- device scratch (no allocations allowed) ----------------
__device__ __align__(16) __half g_cheb[(size_t)IN_F * B_SZ * K8]; // 8 MB, [col][batch][k]
__device__ int g_count[OUT_F];
__device__ int g_start[OUT_F];
__device__ int g_cursor[OUT_F];
__device__ int g_perm[NNZ];

// ---------------- K1: Chebyshev basis table (fp16) ----------------
// cheb[b,c,k] = T_k(clip(tanh(x[b,c])))  via recurrence (== cos(k*arccos(t)))
__global__ void cheb_kernel(const float* __restrict__ x) {
    int idx = blockIdx.x * blockDim.x + threadIdx.x;   // 0 .. B*IN_F-1
    if (idx < OUT_F) g_count[idx] = 0;                 // piggyback: zero histogram
    if (idx >= B_SZ * IN_F) return;
    int b = idx >> 13;          // / IN_F
    int c = idx & (IN_F - 1);
    const float CLIP = 1.0f - 1e-7f;
    float t = tanhf(x[idx]);
    t = fminf(fmaxf(t, -CLIP), CLIP);

    __align__(16) __half h[K8];
    float Tm1 = 1.0f, Tk = t;
    h[0] = __float2half_rn(1.0f);
    h[1] = __float2half_rn(t);
#pragma unroll
    for (int k = 2; k < K8; k++) {
        float Tn = 2.0f * t * Tk - Tm1;
        h[k] = __float2half_rn(Tn);
        Tm1 = Tk; Tk = Tn;
    }
    // layout: [c][b][k] halves -> 16B per (c,b)
    *reinterpret_cast<uint4*>(&g_cheb[((size_t)c * B_SZ + b) * K8]) =
        *reinterpret_cast<const uint4*>(h);
}

// ---------------- K2: histogram of rows ----------------
__global__ void hist_kernel(const int* __restrict__ rows) {
    int i = blockIdx.x * blockDim.x + threadIdx.x;
    if (i < NNZ) atomicAdd(&g_count[rows[i]], 1);
}

// ---------------- K3: exclusive scan over 8192 counters (1 CTA) ----------------
__global__ void scan_kernel() {
    __shared__ int s[1024];
    int t = threadIdx.x;
    int base = t * 8;
    int v[8];
    int run = 0;
#pragma unroll
    for (int i = 0; i < 8; i++) {
        int x = g_count[base + i];
        v[i] = run;            // exclusive within thread
        run += x;
    }
    s[t] = run;
    __syncthreads();
    // Hillis-Steele inclusive scan over 1024 thread totals
    for (int off = 1; off < 1024; off <<= 1) {
        int x = (t >= off) ? s[t - off] : 0;
        __syncthreads();
        s[t] += x;
        __syncthreads();
    }
    int boff = (t > 0) ? s[t - 1] : 0;  // exclusive block offset
#pragma unroll
    for (int i = 0; i < 8; i++) {
        int st = boff + v[i];
        g_start[base + i]  = st;
        g_cursor[base + i] = st;
    }
}

// ---------------- K4: scatter edge ids into row buckets ----------------
__global__ void scatter_kernel(const int* __restrict__ rows) {
    int i = blockIdx.x * blockDim.x + threadIdx.x;
    if (i < NNZ) {
        int p = atomicAdd(&g_cursor[rows[i]], 1);
        g_perm[p] = i;
    }
}

// ---------------- K5: main SpMM — one warp per output row ----------------
// lane l owns batches (2l, 2l+1). Per edge: 32B fp16 basis per lane
// (warp reads one contiguous 1KB line), 32B weight broadcast, 32 FMAs.
__global__ void __launch_bounds__(128) spmm_kernel(const float* __restrict__ weight,
                                                   const int*   __restrict__ cols,
                                                   float* __restrict__ out) {
    int warp = (blockIdx.x * blockDim.x + threadIdx.x) >> 5;
    int lane = threadIdx.x & 31;
    if (warp >= OUT_F) return;
    int r = warp;
    int start = g_start[r];
    int n     = g_count[r];

    float acc0 = 0.0f, acc1 = 0.0f;

    for (int j = 0; j < n; j++) {
        int e = g_perm[start + j];          // uniform across warp -> broadcast
        int c = cols[e];                    // uniform
        const float4* wp = reinterpret_cast<const float4*>(weight + (size_t)e * K8);
        float4 w0 = __ldg(wp);
        float4 w1 = __ldg(wp + 1);

        const uint4* cp = reinterpret_cast<const uint4*>(
            &g_cheb[((size_t)c * B_SZ + 2 * lane) * K8]);
        uint4 ch0 = cp[0];   // batch 2l  : 8 halves
        uint4 ch1 = cp[1];   // batch 2l+1: 8 halves

        const __half2* h0 = reinterpret_cast<const __half2*>(&ch0);
        const __half2* h1 = reinterpret_cast<const __half2*>(&ch1);

        float2 p;
        p = __half22float2(h0[0]); acc0 = fmaf(p.x, w0.x, acc0); acc0 = fmaf(p.y, w0.y, acc0);
        p = __half22float2(h0[1]); acc0 = fmaf(p.x, w0.z, acc0); acc0 = fmaf(p.y, w0.w, acc0);
        p = __half22float2(h0[2]); acc0 = fmaf(p.x, w1.x, acc0); acc0 = fmaf(p.y, w1.y, acc0);
        p = __half22float2(h0[3]); acc0 = fmaf(p.x, w1.z, acc0); acc0 = fmaf(p.y, w1.w, acc0);

        p = __half22float2(h1[0]); acc1 = fmaf(p.x, w0.x, acc1); acc1 = fmaf(p.y, w0.y, acc1);
        p = __half22float2(h1[1]); acc1 = fmaf(p.x, w0.z, acc1); acc1 = fmaf(p.y, w0.w, acc1);
        p = __half22float2(h1[2]); acc1 = fmaf(p.x, w1.x, acc1); acc1 = fmaf(p.y, w1.y, acc1);
        p = __half22float2(h1[3]); acc1 = fmaf(p.x, w1.z, acc1); acc1 = fmaf(p.y, w1.w, acc1);
    }

    // out is [B][OUT_F]; every (b,r) written exactly once (zeros for empty rows)
    out[(size_t)(2 * lane)     * OUT_F + r] = acc0;
    out[(size_t)(2 * lane + 1) * OUT_F + r] = acc1;
}

// ---------------- launcher ----------------
extern "C" void kernel_launch(void* const* d_in, const int* in_sizes, int n_in,
                              void* d_out, int out_size) {
    const float* x      = (const float*)d_in[0];   // [64, 8192]
    const float* weight = (const float*)d_in[1];   // [262144, 8]
    const int*   rows   = (const int*)  d_in[2];   // [262144]
    const int*   cols   = (const int*)  d_in[3];   // [262144]
    float*       out    = (float*)d_out;           // [64, 8192]

    cheb_kernel   <<<(B_SZ * IN_F + 255) / 256, 256>>>(x);
    hist_kernel   <<<(NNZ + 255) / 256, 256>>>(rows);
    scan_kernel   <<<1, 1024>>>();
    scatter_kernel<<<(NNZ + 255) / 256, 256>>>(rows);
    spmm_kernel   <<<(OUT_F * 32 + 127) / 128, 128>>>(weight, cols, out);
}